// round 13
// baseline (speedup 1.0000x reference)
#include <cuda_runtime.h>
#include <cuda_fp16.h>

#define NN      131072
#define KK      27
#define C       32
#define NCOL    (KK * C)           // 864 contrib columns
#define NKTOT   (NN * KK)
#define NCH     4                  // n-chunks; contrib slice 56.6 MB = L2-resident
#define CHN     (NN / NCH)         // 32768 rows per chunk
#define CCAP    28                 // per-(node, chunk) bucket cap (Poisson 6.75)
#define EPS_F   1e-5f
#define CGB     (CHN / 128)        // 256 GEMM CTAs per chunk
#define FILL_BLKS (NKTOT / 4 / 256)
#define GB2     (NN / 8)           // final gather blocks = BN partial count
#define MIDB    256

// -------- device scratch --------
__device__ __align__(16) __half g_contrib16[(size_t)NKTOT * C];      // 226 MB
__device__ int    g_fill[NN * NCH];
__device__ __align__(16) int g_clist[(size_t)NN * NCH * CCAP];       // 58.7 MB buckets
__device__ float  g_part[GB2 * 64];
__device__ float  g_part2[MIDB * 64];
__device__ float  g_stats[64];
__device__ __align__(16) unsigned g_bfrag[108 * 2 * 32 * 2];         // 55 KB: B frag order

__device__ __forceinline__ unsigned smem_u32(const void* p) {
    unsigned a;
    asm("{ .reg .u64 t; cvta.to.shared.u64 t, %1; cvt.u32.u64 %0, t; }" : "=r"(a) : "l"(p));
    return a;
}

// -------- 1. init: zero 4-way counters + pre-swizzle B into mma frag order --
// Bfrag[nt][s][lane][reg]: k0 = s*16 + (l&3)*2 + reg*8, n = nt*8 + (l>>2),
// value half2( B[k0][n], B[k0+1][n] ), B[i][j] = weight[j/32][i][j%32].
__global__ void k_init(const float* __restrict__ weight) {
    int i = blockIdx.x * blockDim.x + threadIdx.x;       // grid covers NN*NCH
    g_fill[i] = 0;
    if (i < 108 * 2 * 32 * 2) {
        int reg = i & 1, l = (i >> 1) & 31, s = (i >> 6) & 1, nt = i >> 7;
        int k0 = s * 16 + (l & 3) * 2 + reg * 8;
        int n  = nt * 8 + (l >> 2);
        int jk = n >> 5, o = n & 31;
        float lo = weight[(jk * 32 + k0) * 32 + o];
        float hi = weight[(jk * 32 + k0 + 1) * 32 + o];
        __half2 h = __floats2half2_rn(lo, hi);
        g_bfrag[i] = *reinterpret_cast<unsigned*>(&h);
    }
}

// -------- 2. chunk worker: GEMM rows [n0, n0+32768) (+ fill on launch 0) ----
// GEMM verbatim R4 (column perm p = j*8 + t*2 + b <-> o = t*8 + j*2 + b);
// plain stores so the chunk's contrib slice stays L2-resident for its gather.
// Fill blocks (only present in the chunk-0 launch) bucket entries by
// (m, chunk_of_n) with chunk = n >> 15.
__global__ __launch_bounds__(256) void k_work(const float* __restrict__ data,
                                              const int* __restrict__ neigh,
                                              int n0) {
    __shared__ __align__(16) __half Ah[128][40];
    const int tid = threadIdx.x, lane = tid & 31, warp = tid >> 5;

    if (blockIdx.x >= CGB) {
        int t = (blockIdx.x - CGB) * 256 + tid;
        int4 m4 = __ldcs(reinterpret_cast<const int4*>(neigh) + t);
        int e0 = t * 4;
#pragma unroll
        for (int q = 0; q < 4; ++q) {
            int m = (q == 0) ? m4.x : (q == 1) ? m4.y : (q == 2) ? m4.z : m4.w;
            int e = e0 + q;
            int n = (int)((unsigned)e / 27u);
            int c = n >> 15;                              // n-chunk id
            int pos = atomicAdd(&g_fill[m * NCH + c], 1);
            if (pos < CCAP)
                __stcs(&g_clist[((size_t)m * NCH + c) * CCAP + pos], e);
        }
        return;
    }

    // ---- GEMM on this chunk's rows ----
    const int nbase = n0 + blockIdx.x * 128;
    const float4* src = reinterpret_cast<const float4*>(data + (size_t)nbase * C);
#pragma unroll
    for (int t0 = 0; t0 < 4; ++t0) {
        int    t = tid + t0 * 256;
        float4 v = src[t];
        int r = t >> 3, c = (t & 7) * 4;
        *reinterpret_cast<__half2*>(&Ah[r][c])     = __floats2half2_rn(v.x, v.y);
        *reinterpret_cast<__half2*>(&Ah[r][c + 2]) = __floats2half2_rn(v.z, v.w);
    }
    __syncthreads();

    unsigned a0[4], a1[4];
    {
        unsigned base = smem_u32(&Ah[warp * 16 + (lane & 15)][(lane >> 4) * 8]);
        asm volatile("ldmatrix.sync.aligned.m8n8.x4.shared.b16 {%0,%1,%2,%3}, [%4];"
                     : "=r"(a0[0]), "=r"(a0[1]), "=r"(a0[2]), "=r"(a0[3]) : "r"(base));
        asm volatile("ldmatrix.sync.aligned.m8n8.x4.shared.b16 {%0,%1,%2,%3}, [%4];"
                     : "=r"(a1[0]), "=r"(a1[1]), "=r"(a1[2]), "=r"(a1[3]) : "r"(base + 32));
    }

    const int r0 = lane >> 2;
    const int j  = lane & 3;
    const size_t nlo = (size_t)nbase + warp * 16 + r0;
    __half* plo = g_contrib16 + nlo * NCOL + j * 8;
    __half* phi = plo + (size_t)8 * NCOL;
    const uint2* bf = reinterpret_cast<const uint2*>(g_bfrag) + lane;

    for (int kb = 0; kb < 27; ++kb) {
        uint2 b[8];
#pragma unroll
        for (int q = 0; q < 8; ++q) b[q] = bf[(kb * 8 + q) * 32];

        unsigned hlo[4], hhi[4];
#pragma unroll
        for (int t = 0; t < 4; ++t) {
            float d0 = 0.f, d1 = 0.f, d2 = 0.f, d3 = 0.f;
            asm volatile(
                "mma.sync.aligned.m16n8k16.row.col.f32.f16.f16.f32 "
                "{%0,%1,%2,%3}, {%4,%5,%6,%7}, {%8,%9}, {%0,%1,%2,%3};"
                : "+f"(d0), "+f"(d1), "+f"(d2), "+f"(d3)
                : "r"(a0[0]), "r"(a0[1]), "r"(a0[2]), "r"(a0[3]),
                  "r"(b[t * 2].x), "r"(b[t * 2].y));
            asm volatile(
                "mma.sync.aligned.m16n8k16.row.col.f32.f16.f16.f32 "
                "{%0,%1,%2,%3}, {%4,%5,%6,%7}, {%8,%9}, {%0,%1,%2,%3};"
                : "+f"(d0), "+f"(d1), "+f"(d2), "+f"(d3)
                : "r"(a1[0]), "r"(a1[1]), "r"(a1[2]), "r"(a1[3]),
                  "r"(b[t * 2 + 1].x), "r"(b[t * 2 + 1].y));
            __half2 l2 = __floats2half2_rn(d0, d1);
            __half2 h2 = __floats2half2_rn(d2, d3);
            hlo[t] = *reinterpret_cast<unsigned*>(&l2);
            hhi[t] = *reinterpret_cast<unsigned*>(&h2);
        }
        *reinterpret_cast<uint4*>(plo + kb * 32) = make_uint4(hlo[0], hlo[1], hlo[2], hlo[3]);
        *reinterpret_cast<uint4*>(phi + kb * 32) = make_uint4(hhi[0], hhi[1], hhi[2], hhi[3]);
    }
}

// -------- 3. chunk gather: sum bucket (m, c) from the L2-hot contrib slice --
// warp = node; lanes 0-15 entry A / 16-31 entry B per pair, half2 per lane.
// FIRST chunk writes out; later chunks accumulate; FINAL emits BN partials.
template <bool FIRST, bool FINAL>
__global__ __launch_bounds__(256) void k_gpass(float* __restrict__ out, int c) {
    __shared__ float sm[8][33];
    const int tid = threadIdx.x, lane = tid & 31, w = tid >> 5;
    const int m = blockIdx.x * 8 + w;
    const int hsel = lane >> 4;
    const int ch2  = lane & 15;
    int cnt = g_fill[m * NCH + c];
    if (cnt > CCAP) cnt = CCAP;
    const int* lst = g_clist + ((size_t)m * NCH + c) * CCAP;

    float2 acc = make_float2(0.f, 0.f);
    int j = 0;
    for (; j + 8 <= cnt; j += 8) {
        __half2 v[4];
#pragma unroll
        for (int t = 0; t < 4; ++t) {
            int e = lst[j + 2 * t + hsel];
            v[t]  = *reinterpret_cast<const __half2*>(
                        g_contrib16 + (size_t)e * C + ch2 * 2);
        }
#pragma unroll
        for (int t = 0; t < 4; ++t) {
            float2 f = __half22float2(v[t]);
            acc.x += f.x; acc.y += f.y;
        }
    }
    for (; j + 2 <= cnt; j += 2) {
        int     e = lst[j + hsel];
        __half2 v = *reinterpret_cast<const __half2*>(
                        g_contrib16 + (size_t)e * C + ch2 * 2);
        float2  f = __half22float2(v);
        acc.x += f.x; acc.y += f.y;
    }
    if (j < cnt && hsel == 0) {
        int     e = lst[j];
        __half2 v = *reinterpret_cast<const __half2*>(
                        g_contrib16 + (size_t)e * C + ch2 * 2);
        float2  f = __half22float2(v);
        acc.x += f.x; acc.y += f.y;
    }
    acc.x += __shfl_down_sync(0xffffffffu, acc.x, 16);
    acc.y += __shfl_down_sync(0xffffffffu, acc.y, 16);

    if (hsel == 0) {
        // undo GEMM column permutation: half2 idx p2 -> channel (p2&3)*8+(p2>>2)*2
        int co = (ch2 & 3) * 8 + (ch2 >> 2) * 2;
        float2* po = reinterpret_cast<float2*>(out + (size_t)m * C + co);
        if (!FIRST) {
            float2 prev = *po;
            acc.x += prev.x; acc.y += prev.y;
        }
        *po = acc;
        if (FINAL) { sm[w][co] = acc.x; sm[w][co + 1] = acc.y; }
    }
    if (FINAL) {
        __syncthreads();
        if (tid < 32) {                  // deterministic per-CTA BN partials
            float s = 0.f, q = 0.f;
#pragma unroll
            for (int r = 0; r < 8; ++r) {
                float v = sm[r][tid];
                s += v; q += v * v;
            }
            g_part[blockIdx.x * 64 + tid]      = s;
            g_part[blockIdx.x * 64 + 32 + tid] = q;
        }
    }
}

// -------- 4. BN partial reduction: 16384 -> 256 --------
__global__ __launch_bounds__(256) void k_bnmid() {
    __shared__ float ss[8][32], sq[8][32];
    int ch = threadIdx.x & 31, w = threadIdx.x >> 5;
    float s = 0.f, q = 0.f;
    for (int p = blockIdx.x * 64 + w; p < (blockIdx.x + 1) * 64; p += 8) {
        s += g_part[p * 64 + ch];
        q += g_part[p * 64 + 32 + ch];
    }
    ss[w][ch] = s; sq[w][ch] = q;
    __syncthreads();
    if (w == 0) {
        float S = 0.f, Q = 0.f;
#pragma unroll
        for (int t = 0; t < 8; ++t) { S += ss[t][ch]; Q += sq[t][ch]; }
        g_part2[blockIdx.x * 64 + ch]      = S;
        g_part2[blockIdx.x * 64 + 32 + ch] = Q;
    }
}

// -------- 5. BN finalize --------
__global__ __launch_bounds__(256) void k_bnfinal(const float* __restrict__ gamma,
                                                 const float* __restrict__ beta) {
    __shared__ float ss[8][32], sq[8][32];
    int ch = threadIdx.x & 31, w = threadIdx.x >> 5;
    float S = 0.f, Q = 0.f;
    for (int b = w; b < MIDB; b += 8) {
        S += g_part2[b * 64 + ch];
        Q += g_part2[b * 64 + 32 + ch];
    }
    ss[w][ch] = S; sq[w][ch] = Q;
    __syncthreads();
    if (w == 0) {
        float St = 0.f, Qt = 0.f;
#pragma unroll
        for (int t = 0; t < 8; ++t) { St += ss[t][ch]; Qt += sq[t][ch]; }
        float mean  = St * (1.0f / NN);
        float var   = Qt * (1.0f / NN) - mean * mean;
        float rstd  = rsqrtf(var + EPS_F);
        float scale = gamma[ch] * rstd;
        g_stats[ch]      = scale;
        g_stats[32 + ch] = beta[ch] - mean * scale;
    }
}

// -------- 6. apply BN + ReLU --------
__global__ __launch_bounds__(256) void k_apply(float* __restrict__ out) {
    int i = blockIdx.x * blockDim.x + threadIdx.x;
    if (i >= NN * C) return;
    int   ch = i & 31;
    float y  = fmaf(out[i], g_stats[ch], g_stats[32 + ch]);
    out[i] = fmaxf(y, 0.f);
}

extern "C" void kernel_launch(void* const* d_in, const int* in_sizes, int n_in,
                              void* d_out, int out_size) {
    const float* data   = (const float*)d_in[0];
    const float* weight = (const float*)d_in[1];
    const float* gamma  = (const float*)d_in[2];
    const float* beta   = (const float*)d_in[3];
    const int*   neigh  = (const int*)d_in[4];
    float*       out    = (float*)d_out;

    k_init<<<NN * NCH / 256, 256>>>(weight);
    // chunk 0: GEMM + fill overlapped
    k_work<<<CGB + FILL_BLKS, 256>>>(data, neigh, 0);
    k_gpass<true,  false><<<GB2, 256>>>(out, 0);
    k_work<<<CGB, 256>>>(data, neigh, 1 * CHN);
    k_gpass<false, false><<<GB2, 256>>>(out, 1);
    k_work<<<CGB, 256>>>(data, neigh, 2 * CHN);
    k_gpass<false, false><<<GB2, 256>>>(out, 2);
    k_work<<<CGB, 256>>>(data, neigh, 3 * CHN);
    k_gpass<false, true ><<<GB2, 256>>>(out, 3);
    k_bnmid<<<MIDB, 256>>>();
    k_bnfinal<<<1, 256>>>(gamma, beta);
    k_apply<<<(NN * C + 255) / 256, 256>>>(out);
}

// round 15
// speedup vs baseline: 1.5524x; 1.5524x over previous
#include <cuda_runtime.h>
#include <cuda_fp16.h>

#define NN      131072
#define KK      27
#define C       32
#define NCOL    (KK * C)           // 864 contrib columns
#define NKTOT   (NN * KK)          // row NKTOT of contrib = zero sentinel
#define DCAP    64                 // dense bucket width (Poisson(27), P(cnt>64) ~ 1e-9)
#define EPS_F   1e-5f
#define GEMM_BLKS 1024             // NN/128
#define FILL_BLKS (NKTOT / 4 / 256)
#define GB      8192               // gather blocks = BN partial count
#define MIDB    256

// -------- device scratch --------
__device__ __align__(16) __half g_contrib16[(size_t)NKTOT * C + C];  // 226 MB + sentinel row
__device__ int    g_fill[NN];
__device__ __align__(16) int g_dense[(size_t)NN * DCAP];             // 33.5 MB buckets
__device__ float  g_part[GB * 64];
__device__ float  g_part2[MIDB * 64];
__device__ float  g_stats[64];
__device__ __align__(16) unsigned g_bfrag[108 * 2 * 32 * 2];         // 55 KB: B frag order

__device__ __forceinline__ unsigned smem_u32(const void* p) {
    unsigned a;
    asm("{ .reg .u64 t; cvta.to.shared.u64 t, %1; cvt.u32.u64 %0, t; }" : "=r"(a) : "l"(p));
    return a;
}

// -------- 1. init: zero fill counters, zero sentinel row, B->mma frags ------
// Bfrag[nt][s][lane][reg]: k0 = s*16 + (l&3)*2 + reg*8, n = nt*8 + (l>>2),
// value half2( B[k0][n], B[k0+1][n] ), B[i][j] = weight[j/32][i][j%32].
__global__ void k_init(const float* __restrict__ weight) {
    int i = blockIdx.x * blockDim.x + threadIdx.x;
    if (i < NN) g_fill[i] = 0;
    if (i < 4) reinterpret_cast<uint4*>(g_contrib16 + (size_t)NKTOT * C)[i] =
        make_uint4(0u, 0u, 0u, 0u);
    if (i < 108 * 2 * 32 * 2) {
        int reg = i & 1, l = (i >> 1) & 31, s = (i >> 6) & 1, nt = i >> 7;
        int k0 = s * 16 + (l & 3) * 2 + reg * 8;
        int n  = nt * 8 + (l >> 2);
        int jk = n >> 5, o = n & 31;
        float lo = weight[(jk * 32 + k0) * 32 + o];
        float hi = weight[(jk * 32 + k0 + 1) * 32 + o];
        __half2 h = __floats2half2_rn(lo, hi);
        g_bfrag[i] = *reinterpret_cast<unsigned*>(&h);
    }
}

// -------- 2. merged work kernel: GEMM (blocks 0..1023) + fill (rest) --------
// Verbatim from the verified R4/R8 kernel.
// Column perm within each 32-wide k-block: p = j*8 + t*2 + b <-> o = t*8+j*2+b.
__global__ __launch_bounds__(256) void k_work(const float* __restrict__ data,
                                              const int* __restrict__ neigh) {
    __shared__ __align__(16) __half Ah[128][40];
    const int tid = threadIdx.x, lane = tid & 31, warp = tid >> 5;

    if (blockIdx.x >= GEMM_BLKS) {
        // ---- fill: build dense inverse index ----
        int t = (blockIdx.x - GEMM_BLKS) * 256 + tid;
        int4 m4 = __ldcs(reinterpret_cast<const int4*>(neigh) + t);
        int e0 = t * 4;
#pragma unroll
        for (int q = 0; q < 4; ++q) {
            int m   = (q == 0) ? m4.x : (q == 1) ? m4.y : (q == 2) ? m4.z : m4.w;
            int pos = atomicAdd(&g_fill[m], 1);
            if (pos < DCAP) __stcs(&g_dense[(size_t)m * DCAP + pos], e0 + q);
        }
        return;
    }

    // ---- GEMM ----
    const int bid = blockIdx.x;
    const float4* src = reinterpret_cast<const float4*>(data + (size_t)bid * 128 * C);
#pragma unroll
    for (int t0 = 0; t0 < 4; ++t0) {
        int    t = tid + t0 * 256;
        float4 v = src[t];
        int r = t >> 3, c = (t & 7) * 4;
        *reinterpret_cast<__half2*>(&Ah[r][c])     = __floats2half2_rn(v.x, v.y);
        *reinterpret_cast<__half2*>(&Ah[r][c + 2]) = __floats2half2_rn(v.z, v.w);
    }
    __syncthreads();

    unsigned a0[4], a1[4];
    {
        unsigned base = smem_u32(&Ah[warp * 16 + (lane & 15)][(lane >> 4) * 8]);
        asm volatile("ldmatrix.sync.aligned.m8n8.x4.shared.b16 {%0,%1,%2,%3}, [%4];"
                     : "=r"(a0[0]), "=r"(a0[1]), "=r"(a0[2]), "=r"(a0[3]) : "r"(base));
        asm volatile("ldmatrix.sync.aligned.m8n8.x4.shared.b16 {%0,%1,%2,%3}, [%4];"
                     : "=r"(a1[0]), "=r"(a1[1]), "=r"(a1[2]), "=r"(a1[3]) : "r"(base + 32));
    }

    const int r0 = lane >> 2;
    const int j  = lane & 3;
    const size_t nlo = (size_t)bid * 128 + warp * 16 + r0;
    __half* plo = g_contrib16 + nlo * NCOL + j * 8;
    __half* phi = plo + (size_t)8 * NCOL;
    const uint2* bf = reinterpret_cast<const uint2*>(g_bfrag) + lane;

    for (int kb = 0; kb < 27; ++kb) {
        uint2 b[8];
#pragma unroll
        for (int q = 0; q < 8; ++q) b[q] = bf[(kb * 8 + q) * 32];

        unsigned hlo[4], hhi[4];
#pragma unroll
        for (int t = 0; t < 4; ++t) {
            float d0 = 0.f, d1 = 0.f, d2 = 0.f, d3 = 0.f;
            asm volatile(
                "mma.sync.aligned.m16n8k16.row.col.f32.f16.f16.f32 "
                "{%0,%1,%2,%3}, {%4,%5,%6,%7}, {%8,%9}, {%0,%1,%2,%3};"
                : "+f"(d0), "+f"(d1), "+f"(d2), "+f"(d3)
                : "r"(a0[0]), "r"(a0[1]), "r"(a0[2]), "r"(a0[3]),
                  "r"(b[t * 2].x), "r"(b[t * 2].y));
            asm volatile(
                "mma.sync.aligned.m16n8k16.row.col.f32.f16.f16.f32 "
                "{%0,%1,%2,%3}, {%4,%5,%6,%7}, {%8,%9}, {%0,%1,%2,%3};"
                : "+f"(d0), "+f"(d1), "+f"(d2), "+f"(d3)
                : "r"(a1[0]), "r"(a1[1]), "r"(a1[2]), "r"(a1[3]),
                  "r"(b[t * 2 + 1].x), "r"(b[t * 2 + 1].y));
            __half2 l2 = __floats2half2_rn(d0, d1);
            __half2 h2 = __floats2half2_rn(d2, d3);
            hlo[t] = *reinterpret_cast<unsigned*>(&l2);
            hhi[t] = *reinterpret_cast<unsigned*>(&h2);
        }
        uint4 vlo = make_uint4(hlo[0], hlo[1], hlo[2], hlo[3]);
        uint4 vhi = make_uint4(hhi[0], hhi[1], hhi[2], hhi[3]);
        __stcs(reinterpret_cast<uint4*>(plo + kb * 32), vlo);
        __stcs(reinterpret_cast<uint4*>(phi + kb * 32), vhi);
    }
}

// -------- 3. gather + BN stage-1: warp = node, 16-entry MLP body ------------
// lane: g = lane>>3 selects entry-of-4 per instruction, c = lane&7 reads 8B.
// Body = 16 entries: 4 bcast int4 list loads + 16 independent 64B-row loads
// (predicated to the zero sentinel row past cnt). Register accumulate,
// shfl-tree reduce, permuted channel write, per-CTA deterministic BN partials.
__global__ __launch_bounds__(512) void k_gather(float* __restrict__ out) {
    __shared__ float sm[16][33];
    const int tid = threadIdx.x, lane = tid & 31, w = tid >> 5;
    const int m = blockIdx.x * 16 + w;
    const int g = lane >> 3, c = lane & 7;

    int cnt = g_fill[m];
    if (cnt > DCAP) cnt = DCAP;
    const int* dl = g_dense + (size_t)m * DCAP;

    float4 acc = make_float4(0.f, 0.f, 0.f, 0.f);
    for (int j = 0; j < cnt; j += 16) {
        int4 ea = *reinterpret_cast<const int4*>(dl + j);
        int4 eb = *reinterpret_cast<const int4*>(dl + j + 4);
        int4 ec = *reinterpret_cast<const int4*>(dl + j + 8);
        int4 ed = *reinterpret_cast<const int4*>(dl + j + 12);
        int e1 = (g == 0) ? ea.x : (g == 1) ? ea.y : (g == 2) ? ea.z : ea.w;
        int e2 = (g == 0) ? eb.x : (g == 1) ? eb.y : (g == 2) ? eb.z : eb.w;
        int e3 = (g == 0) ? ec.x : (g == 1) ? ec.y : (g == 2) ? ec.z : ec.w;
        int e4 = (g == 0) ? ed.x : (g == 1) ? ed.y : (g == 2) ? ed.z : ed.w;
        e1 = (j + g      < cnt) ? e1 : NKTOT;      // sentinel -> zero row
        e2 = (j + 4 + g  < cnt) ? e2 : NKTOT;
        e3 = (j + 8 + g  < cnt) ? e3 : NKTOT;
        e4 = (j + 12 + g < cnt) ? e4 : NKTOT;
        uint2 d1 = __ldcs(reinterpret_cast<const uint2*>(g_contrib16 + (size_t)e1 * C) + c);
        uint2 d2 = __ldcs(reinterpret_cast<const uint2*>(g_contrib16 + (size_t)e2 * C) + c);
        uint2 d3 = __ldcs(reinterpret_cast<const uint2*>(g_contrib16 + (size_t)e3 * C) + c);
        uint2 d4 = __ldcs(reinterpret_cast<const uint2*>(g_contrib16 + (size_t)e4 * C) + c);
        float2 f;
        f = __half22float2(*reinterpret_cast<__half2*>(&d1.x)); acc.x += f.x; acc.y += f.y;
        f = __half22float2(*reinterpret_cast<__half2*>(&d1.y)); acc.z += f.x; acc.w += f.y;
        f = __half22float2(*reinterpret_cast<__half2*>(&d2.x)); acc.x += f.x; acc.y += f.y;
        f = __half22float2(*reinterpret_cast<__half2*>(&d2.y)); acc.z += f.x; acc.w += f.y;
        f = __half22float2(*reinterpret_cast<__half2*>(&d3.x)); acc.x += f.x; acc.y += f.y;
        f = __half22float2(*reinterpret_cast<__half2*>(&d3.y)); acc.z += f.x; acc.w += f.y;
        f = __half22float2(*reinterpret_cast<__half2*>(&d4.x)); acc.x += f.x; acc.y += f.y;
        f = __half22float2(*reinterpret_cast<__half2*>(&d4.y)); acc.z += f.x; acc.w += f.y;
    }
    // reduce 4 groups -> lanes 0-7
    acc.x += __shfl_down_sync(0xffffffffu, acc.x, 8);
    acc.y += __shfl_down_sync(0xffffffffu, acc.y, 8);
    acc.z += __shfl_down_sync(0xffffffffu, acc.z, 8);
    acc.w += __shfl_down_sync(0xffffffffu, acc.w, 8);
    acc.x += __shfl_down_sync(0xffffffffu, acc.x, 16);
    acc.y += __shfl_down_sync(0xffffffffu, acc.y, 16);
    acc.z += __shfl_down_sync(0xffffffffu, acc.z, 16);
    acc.w += __shfl_down_sync(0xffffffffu, acc.w, 16);

    if (lane < 8) {
        // undo column permutation: half2 idx p2 -> channel (p2&3)*8 + (p2>>2)*2
        int co0 = ((2 * c)     & 3) * 8 + ((2 * c)     >> 2) * 2;
        int co1 = ((2 * c + 1) & 3) * 8 + ((2 * c + 1) >> 2) * 2;
        *reinterpret_cast<float2*>(out + (size_t)m * C + co0) = make_float2(acc.x, acc.y);
        *reinterpret_cast<float2*>(out + (size_t)m * C + co1) = make_float2(acc.z, acc.w);
        sm[w][co0] = acc.x; sm[w][co0 + 1] = acc.y;
        sm[w][co1] = acc.z; sm[w][co1 + 1] = acc.w;
    }
    __syncthreads();
    if (tid < 32) {                      // deterministic per-CTA BN partials
        float s = 0.f, q = 0.f;
#pragma unroll
        for (int r = 0; r < 16; ++r) {
            float v = sm[r][tid];
            s += v; q += v * v;
        }
        g_part[blockIdx.x * 64 + tid]      = s;
        g_part[blockIdx.x * 64 + 32 + tid] = q;
    }
}

// -------- 4. BN partial reduction: 8192 -> 256 --------
__global__ __launch_bounds__(256) void k_bnmid() {
    __shared__ float ss[8][32], sq[8][32];
    int ch = threadIdx.x & 31, w = threadIdx.x >> 5;
    float s = 0.f, q = 0.f;
    for (int p = blockIdx.x * 32 + w; p < (blockIdx.x + 1) * 32; p += 8) {
        s += g_part[p * 64 + ch];
        q += g_part[p * 64 + 32 + ch];
    }
    ss[w][ch] = s; sq[w][ch] = q;
    __syncthreads();
    if (w == 0) {
        float S = 0.f, Q = 0.f;
#pragma unroll
        for (int t = 0; t < 8; ++t) { S += ss[t][ch]; Q += sq[t][ch]; }
        g_part2[blockIdx.x * 64 + ch]      = S;
        g_part2[blockIdx.x * 64 + 32 + ch] = Q;
    }
}

// -------- 5. BN finalize --------
__global__ __launch_bounds__(256) void k_bnfinal(const float* __restrict__ gamma,
                                                 const float* __restrict__ beta) {
    __shared__ float ss[8][32], sq[8][32];
    int ch = threadIdx.x & 31, w = threadIdx.x >> 5;
    float S = 0.f, Q = 0.f;
    for (int b = w; b < MIDB; b += 8) {
        S += g_part2[b * 64 + ch];
        Q += g_part2[b * 64 + 32 + ch];
    }
    ss[w][ch] = S; sq[w][ch] = Q;
    __syncthreads();
    if (w == 0) {
        float St = 0.f, Qt = 0.f;
#pragma unroll
        for (int t = 0; t < 8; ++t) { St += ss[t][ch]; Qt += sq[t][ch]; }
        float mean  = St * (1.0f / NN);
        float var   = Qt * (1.0f / NN) - mean * mean;
        float rstd  = rsqrtf(var + EPS_F);
        float scale = gamma[ch] * rstd;
        g_stats[ch]      = scale;
        g_stats[32 + ch] = beta[ch] - mean * scale;
    }
}

// -------- 6. apply BN + ReLU --------
__global__ __launch_bounds__(256) void k_apply(float* __restrict__ out) {
    int i = blockIdx.x * blockDim.x + threadIdx.x;
    if (i >= NN * C) return;
    int   ch = i & 31;
    float y  = fmaf(out[i], g_stats[ch], g_stats[32 + ch]);
    out[i] = fmaxf(y, 0.f);
}

extern "C" void kernel_launch(void* const* d_in, const int* in_sizes, int n_in,
                              void* d_out, int out_size) {
    const float* data   = (const float*)d_in[0];
    const float* weight = (const float*)d_in[1];
    const float* gamma  = (const float*)d_in[2];
    const float* beta   = (const float*)d_in[3];
    const int*   neigh  = (const int*)d_in[4];
    float*       out    = (float*)d_out;

    k_init<<<NN / 256, 256>>>(weight);
    k_work<<<GEMM_BLKS + FILL_BLKS, 256>>>(data, neigh);
    k_gather<<<GB, 512>>>(out);
    k_bnmid<<<MIDB, 256>>>();
    k_bnfinal<<<1, 256>>>(gamma, beta);
    k_apply<<<(NN * C + 255) / 256, 256>>>(out);
}

// round 16
// speedup vs baseline: 1.6228x; 1.0454x over previous
#include <cuda_runtime.h>
#include <cuda_fp16.h>

#define NN      131072
#define KK      27
#define C       32
#define NCOL    (KK * C)           // 864 contrib columns
#define NKTOT   (NN * KK)          // row NKTOT of contrib = zero sentinel
#define DCAP    64                 // dense bucket width (Poisson(27), P(cnt>64) ~ 1e-9)
#define EPS_F   1e-5f
#define GEMM_BLKS 1024             // NN/128
#define FILL_BLKS (NKTOT / 4 / 256)
#define GB      8192               // gather blocks = BN partial count
#define MIDB    256

// -------- device scratch --------
__device__ __align__(16) __half g_contrib16[(size_t)NKTOT * C + C];  // 226 MB + sentinel row
__device__ int    g_fill[NN];
__device__ __align__(16) int g_dense[(size_t)NN * DCAP];             // 33.5 MB buckets
__device__ float  g_part[GB * 64];
__device__ float  g_part2[MIDB * 64];
__device__ float  g_stats[64];
__device__ __align__(16) unsigned g_bfrag[108 * 2 * 32 * 2];         // 55 KB: B frag order

__device__ __forceinline__ unsigned smem_u32(const void* p) {
    unsigned a;
    asm("{ .reg .u64 t; cvta.to.shared.u64 t, %1; cvt.u32.u64 %0, t; }" : "=r"(a) : "l"(p));
    return a;
}

// -------- 1. init: zero fill counters, zero sentinel row, B->mma frags ------
// Bfrag[nt][s][lane][reg]: k0 = s*16 + (l&3)*2 + reg*8, n = nt*8 + (l>>2),
// value half2( B[k0][n], B[k0+1][n] ), B[i][j] = weight[j/32][i][j%32].
__global__ void k_init(const float* __restrict__ weight) {
    int i = blockIdx.x * blockDim.x + threadIdx.x;
    if (i < NN) g_fill[i] = 0;
    if (i < 4) reinterpret_cast<uint4*>(g_contrib16 + (size_t)NKTOT * C)[i] =
        make_uint4(0u, 0u, 0u, 0u);
    if (i < 108 * 2 * 32 * 2) {
        int reg = i & 1, l = (i >> 1) & 31, s = (i >> 6) & 1, nt = i >> 7;
        int k0 = s * 16 + (l & 3) * 2 + reg * 8;
        int n  = nt * 8 + (l >> 2);
        int jk = n >> 5, o = n & 31;
        float lo = weight[(jk * 32 + k0) * 32 + o];
        float hi = weight[(jk * 32 + k0 + 1) * 32 + o];
        __half2 h = __floats2half2_rn(lo, hi);
        g_bfrag[i] = *reinterpret_cast<unsigned*>(&h);
    }
}

// -------- 2. merged work kernel: GEMM (blocks 0..1023) + fill (rest) --------
// Verbatim from the verified R4/R8 kernel.
// Column perm within each 32-wide k-block: p = j*8 + t*2 + b <-> o = t*8+j*2+b.
__global__ __launch_bounds__(256) void k_work(const float* __restrict__ data,
                                              const int* __restrict__ neigh) {
    __shared__ __align__(16) __half Ah[128][40];
    const int tid = threadIdx.x, lane = tid & 31, warp = tid >> 5;

    if (blockIdx.x >= GEMM_BLKS) {
        // ---- fill: build dense inverse index ----
        int t = (blockIdx.x - GEMM_BLKS) * 256 + tid;
        int4 m4 = __ldcs(reinterpret_cast<const int4*>(neigh) + t);
        int e0 = t * 4;
#pragma unroll
        for (int q = 0; q < 4; ++q) {
            int m   = (q == 0) ? m4.x : (q == 1) ? m4.y : (q == 2) ? m4.z : m4.w;
            int pos = atomicAdd(&g_fill[m], 1);
            if (pos < DCAP) __stcs(&g_dense[(size_t)m * DCAP + pos], e0 + q);
        }
        return;
    }

    // ---- GEMM ----
    const int bid = blockIdx.x;
    const float4* src = reinterpret_cast<const float4*>(data + (size_t)bid * 128 * C);
#pragma unroll
    for (int t0 = 0; t0 < 4; ++t0) {
        int    t = tid + t0 * 256;
        float4 v = src[t];
        int r = t >> 3, c = (t & 7) * 4;
        *reinterpret_cast<__half2*>(&Ah[r][c])     = __floats2half2_rn(v.x, v.y);
        *reinterpret_cast<__half2*>(&Ah[r][c + 2]) = __floats2half2_rn(v.z, v.w);
    }
    __syncthreads();

    unsigned a0[4], a1[4];
    {
        unsigned base = smem_u32(&Ah[warp * 16 + (lane & 15)][(lane >> 4) * 8]);
        asm volatile("ldmatrix.sync.aligned.m8n8.x4.shared.b16 {%0,%1,%2,%3}, [%4];"
                     : "=r"(a0[0]), "=r"(a0[1]), "=r"(a0[2]), "=r"(a0[3]) : "r"(base));
        asm volatile("ldmatrix.sync.aligned.m8n8.x4.shared.b16 {%0,%1,%2,%3}, [%4];"
                     : "=r"(a1[0]), "=r"(a1[1]), "=r"(a1[2]), "=r"(a1[3]) : "r"(base + 32));
    }

    const int r0 = lane >> 2;
    const int j  = lane & 3;
    const size_t nlo = (size_t)bid * 128 + warp * 16 + r0;
    __half* plo = g_contrib16 + nlo * NCOL + j * 8;
    __half* phi = plo + (size_t)8 * NCOL;
    const uint2* bf = reinterpret_cast<const uint2*>(g_bfrag) + lane;

    for (int kb = 0; kb < 27; ++kb) {
        uint2 b[8];
#pragma unroll
        for (int q = 0; q < 8; ++q) b[q] = bf[(kb * 8 + q) * 32];

        unsigned hlo[4], hhi[4];
#pragma unroll
        for (int t = 0; t < 4; ++t) {
            float d0 = 0.f, d1 = 0.f, d2 = 0.f, d3 = 0.f;
            asm volatile(
                "mma.sync.aligned.m16n8k16.row.col.f32.f16.f16.f32 "
                "{%0,%1,%2,%3}, {%4,%5,%6,%7}, {%8,%9}, {%0,%1,%2,%3};"
                : "+f"(d0), "+f"(d1), "+f"(d2), "+f"(d3)
                : "r"(a0[0]), "r"(a0[1]), "r"(a0[2]), "r"(a0[3]),
                  "r"(b[t * 2].x), "r"(b[t * 2].y));
            asm volatile(
                "mma.sync.aligned.m16n8k16.row.col.f32.f16.f16.f32 "
                "{%0,%1,%2,%3}, {%4,%5,%6,%7}, {%8,%9}, {%0,%1,%2,%3};"
                : "+f"(d0), "+f"(d1), "+f"(d2), "+f"(d3)
                : "r"(a1[0]), "r"(a1[1]), "r"(a1[2]), "r"(a1[3]),
                  "r"(b[t * 2 + 1].x), "r"(b[t * 2 + 1].y));
            __half2 l2 = __floats2half2_rn(d0, d1);
            __half2 h2 = __floats2half2_rn(d2, d3);
            hlo[t] = *reinterpret_cast<unsigned*>(&l2);
            hhi[t] = *reinterpret_cast<unsigned*>(&h2);
        }
        uint4 vlo = make_uint4(hlo[0], hlo[1], hlo[2], hlo[3]);
        uint4 vhi = make_uint4(hhi[0], hhi[1], hhi[2], hhi[3]);
        __stcs(reinterpret_cast<uint4*>(plo + kb * 32), vlo);
        __stcs(reinterpret_cast<uint4*>(phi + kb * 32), vhi);
    }
}

// -------- 3. gather + BN stage-1: warp = node, 8-entry body, L2-retaining ---
// lane: g = lane>>3 selects entry-of-4, c = lane&7 reads 8B (4 channels).
// Body = 8 entries: 2 bcast int4 list loads + 8 independent 64B-row loads,
// DEFAULT cache policy (evict-normal) so the unused half of each fetched
// 128B line stays in L2 for other warps. Sentinel row absorbs the tail.
__global__ __launch_bounds__(512) void k_gather(float* __restrict__ out) {
    __shared__ float sm[16][33];
    const int tid = threadIdx.x, lane = tid & 31, w = tid >> 5;
    const int m = blockIdx.x * 16 + w;
    const int g = lane >> 3, c = lane & 7;

    int cnt = g_fill[m];
    if (cnt > DCAP) cnt = DCAP;
    const int* dl = g_dense + (size_t)m * DCAP;

    float4 acc = make_float4(0.f, 0.f, 0.f, 0.f);
    for (int j = 0; j < cnt; j += 8) {
        int4 ea = *reinterpret_cast<const int4*>(dl + j);
        int4 eb = *reinterpret_cast<const int4*>(dl + j + 4);
        int e1 = (g == 0) ? ea.x : (g == 1) ? ea.y : (g == 2) ? ea.z : ea.w;
        int e2 = (g == 0) ? eb.x : (g == 1) ? eb.y : (g == 2) ? eb.z : eb.w;
        e1 = (j + g     < cnt) ? e1 : NKTOT;      // sentinel -> zero row
        e2 = (j + 4 + g < cnt) ? e2 : NKTOT;
        uint2 d1 = *(reinterpret_cast<const uint2*>(g_contrib16 + (size_t)e1 * C) + c);
        uint2 d2 = *(reinterpret_cast<const uint2*>(g_contrib16 + (size_t)e2 * C) + c);
        float2 f;
        f = __half22float2(*reinterpret_cast<__half2*>(&d1.x)); acc.x += f.x; acc.y += f.y;
        f = __half22float2(*reinterpret_cast<__half2*>(&d1.y)); acc.z += f.x; acc.w += f.y;
        f = __half22float2(*reinterpret_cast<__half2*>(&d2.x)); acc.x += f.x; acc.y += f.y;
        f = __half22float2(*reinterpret_cast<__half2*>(&d2.y)); acc.z += f.x; acc.w += f.y;
    }
    // reduce 4 groups -> lanes 0-7
    acc.x += __shfl_down_sync(0xffffffffu, acc.x, 8);
    acc.y += __shfl_down_sync(0xffffffffu, acc.y, 8);
    acc.z += __shfl_down_sync(0xffffffffu, acc.z, 8);
    acc.w += __shfl_down_sync(0xffffffffu, acc.w, 8);
    acc.x += __shfl_down_sync(0xffffffffu, acc.x, 16);
    acc.y += __shfl_down_sync(0xffffffffu, acc.y, 16);
    acc.z += __shfl_down_sync(0xffffffffu, acc.z, 16);
    acc.w += __shfl_down_sync(0xffffffffu, acc.w, 16);

    if (lane < 8) {
        // undo column permutation: half2 idx p2 -> channel (p2&3)*8 + (p2>>2)*2
        int co0 = ((2 * c)     & 3) * 8 + ((2 * c)     >> 2) * 2;
        int co1 = ((2 * c + 1) & 3) * 8 + ((2 * c + 1) >> 2) * 2;
        *reinterpret_cast<float2*>(out + (size_t)m * C + co0) = make_float2(acc.x, acc.y);
        *reinterpret_cast<float2*>(out + (size_t)m * C + co1) = make_float2(acc.z, acc.w);
        sm[w][co0] = acc.x; sm[w][co0 + 1] = acc.y;
        sm[w][co1] = acc.z; sm[w][co1 + 1] = acc.w;
    }
    __syncthreads();
    if (tid < 32) {                      // deterministic per-CTA BN partials
        float s = 0.f, q = 0.f;
#pragma unroll
        for (int r = 0; r < 16; ++r) {
            float v = sm[r][tid];
            s += v; q += v * v;
        }
        g_part[blockIdx.x * 64 + tid]      = s;
        g_part[blockIdx.x * 64 + 32 + tid] = q;
    }
}

// -------- 4. BN partial reduction: 8192 -> 256 --------
__global__ __launch_bounds__(256) void k_bnmid() {
    __shared__ float ss[8][32], sq[8][32];
    int ch = threadIdx.x & 31, w = threadIdx.x >> 5;
    float s = 0.f, q = 0.f;
    for (int p = blockIdx.x * 32 + w; p < (blockIdx.x + 1) * 32; p += 8) {
        s += g_part[p * 64 + ch];
        q += g_part[p * 64 + 32 + ch];
    }
    ss[w][ch] = s; sq[w][ch] = q;
    __syncthreads();
    if (w == 0) {
        float S = 0.f, Q = 0.f;
#pragma unroll
        for (int t = 0; t < 8; ++t) { S += ss[t][ch]; Q += sq[t][ch]; }
        g_part2[blockIdx.x * 64 + ch]      = S;
        g_part2[blockIdx.x * 64 + 32 + ch] = Q;
    }
}

// -------- 5. BN finalize --------
__global__ __launch_bounds__(256) void k_bnfinal(const float* __restrict__ gamma,
                                                 const float* __restrict__ beta) {
    __shared__ float ss[8][32], sq[8][32];
    int ch = threadIdx.x & 31, w = threadIdx.x >> 5;
    float S = 0.f, Q = 0.f;
    for (int b = w; b < MIDB; b += 8) {
        S += g_part2[b * 64 + ch];
        Q += g_part2[b * 64 + 32 + ch];
    }
    ss[w][ch] = S; sq[w][ch] = Q;
    __syncthreads();
    if (w == 0) {
        float St = 0.f, Qt = 0.f;
#pragma unroll
        for (int t = 0; t < 8; ++t) { St += ss[t][ch]; Qt += sq[t][ch]; }
        float mean  = St * (1.0f / NN);
        float var   = Qt * (1.0f / NN) - mean * mean;
        float rstd  = rsqrtf(var + EPS_F);
        float scale = gamma[ch] * rstd;
        g_stats[ch]      = scale;
        g_stats[32 + ch] = beta[ch] - mean * scale;
    }
}

// -------- 6. apply BN + ReLU --------
__global__ __launch_bounds__(256) void k_apply(float* __restrict__ out) {
    int i = blockIdx.x * blockDim.x + threadIdx.x;
    if (i >= NN * C) return;
    int   ch = i & 31;
    float y  = fmaf(out[i], g_stats[ch], g_stats[32 + ch]);
    out[i] = fmaxf(y, 0.f);
}

extern "C" void kernel_launch(void* const* d_in, const int* in_sizes, int n_in,
                              void* d_out, int out_size) {
    const float* data   = (const float*)d_in[0];
    const float* weight = (const float*)d_in[1];
    const float* gamma  = (const float*)d_in[2];
    const float* beta   = (const float*)d_in[3];
    const int*   neigh  = (const int*)d_in[4];
    float*       out    = (float*)d_out;

    k_init<<<NN / 256, 256>>>(weight);
    k_work<<<GEMM_BLKS + FILL_BLKS, 256>>>(data, neigh);
    k_gather<<<GB, 512>>>(out);
    k_bnmid<<<MIDB, 256>>>();
    k_bnfinal<<<1, 256>>>(gamma, beta);
    k_apply<<<(NN * C + 255) / 256, 256>>>(out);
}

// round 17
// speedup vs baseline: 1.9479x; 1.2003x over previous
#include <cuda_runtime.h>
#include <cuda_fp16.h>

#define NN      131072
#define KK      27
#define C       32
#define NCOL    (KK * C)           // 864 contrib columns
#define NKTOT   (NN * KK)          // 3538944 scatter entries
#define CAP     96                 // bucket capacity (Poisson(27), P(overflow) ~ 2.5e-10)
#define BN_BLKS 1024
#define EPS_F   1e-5f
#define GEMM_BLKS 1024             // NN/128
#define FILL_BLKS (NKTOT / 4 / 256)

// -------- device scratch --------
__device__ __align__(16) __half g_contrib16[(size_t)NKTOT * C];  // 226 MB
__device__ int    g_fill[NN];
__device__ __align__(16) int g_list[(size_t)NN * CAP];           // 50 MB inverse index
__device__ float  g_part[BN_BLKS * 64];
__device__ float  g_stats[64];
__device__ __align__(16) unsigned g_bfrag[108 * 2 * 32 * 2];     // 55 KB: B in frag order

__device__ __forceinline__ unsigned smem_u32(const void* p) {
    unsigned a;
    asm("{ .reg .u64 t; cvta.to.shared.u64 t, %1; cvt.u32.u64 %0, t; }" : "=r"(a) : "l"(p));
    return a;
}

// -------- 1. init: zero fill counters + pre-swizzle B into mma frag order ----
// Bfrag[nt][s][lane][reg]: k0 = s*16 + (l&3)*2 + reg*8, n = nt*8 + (l>>2),
// value half2( B[k0][n], B[k0+1][n] ), B[i][j] = weight[j/32][i][j%32].
__global__ void k_init(const float* __restrict__ weight) {
    int i = blockIdx.x * blockDim.x + threadIdx.x;
    if (i < NN) g_fill[i] = 0;
    if (i < 108 * 2 * 32 * 2) {
        int reg = i & 1, l = (i >> 1) & 31, s = (i >> 6) & 1, nt = i >> 7;
        int k0 = s * 16 + (l & 3) * 2 + reg * 8;
        int n  = nt * 8 + (l >> 2);
        int jk = n >> 5, o = n & 31;
        float lo = weight[(jk * 32 + k0) * 32 + o];
        float hi = weight[(jk * 32 + k0 + 1) * 32 + o];
        __half2 h = __floats2half2_rn(lo, hi);
        g_bfrag[i] = *reinterpret_cast<unsigned*>(&h);
    }
}

// -------- 2. merged work kernel: GEMM (blocks 0..1023) + fill (rest) --------
// Verbatim from the 182.7us R4 kernel.
// Column perm within each 32-wide k-block: p = j*8 + t*2 + b <-> o = t*8+j*2+b.
__global__ __launch_bounds__(256) void k_work(const float* __restrict__ data,
                                              const int* __restrict__ neigh) {
    __shared__ __align__(16) __half Ah[128][40];
    const int tid = threadIdx.x, lane = tid & 31, warp = tid >> 5;

    if (blockIdx.x >= GEMM_BLKS) {
        // ---- fill: build inverse index ----
        int t = (blockIdx.x - GEMM_BLKS) * 256 + tid;
        int4 m4 = __ldcs(reinterpret_cast<const int4*>(neigh) + t);
        int e0 = t * 4;
#pragma unroll
        for (int q = 0; q < 4; ++q) {
            int m   = (q == 0) ? m4.x : (q == 1) ? m4.y : (q == 2) ? m4.z : m4.w;
            int pos = atomicAdd(&g_fill[m], 1);
            if (pos < CAP) __stcs(&g_list[(size_t)m * CAP + pos], e0 + q);
        }
        return;
    }

    // ---- GEMM ----
    const int bid = blockIdx.x;
    const float4* src = reinterpret_cast<const float4*>(data + (size_t)bid * 128 * C);
#pragma unroll
    for (int t0 = 0; t0 < 4; ++t0) {
        int    t = tid + t0 * 256;
        float4 v = src[t];
        int r = t >> 3, c = (t & 7) * 4;
        *reinterpret_cast<__half2*>(&Ah[r][c])     = __floats2half2_rn(v.x, v.y);
        *reinterpret_cast<__half2*>(&Ah[r][c + 2]) = __floats2half2_rn(v.z, v.w);
    }
    __syncthreads();

    unsigned a0[4], a1[4];
    {
        unsigned base = smem_u32(&Ah[warp * 16 + (lane & 15)][(lane >> 4) * 8]);
        asm volatile("ldmatrix.sync.aligned.m8n8.x4.shared.b16 {%0,%1,%2,%3}, [%4];"
                     : "=r"(a0[0]), "=r"(a0[1]), "=r"(a0[2]), "=r"(a0[3]) : "r"(base));
        asm volatile("ldmatrix.sync.aligned.m8n8.x4.shared.b16 {%0,%1,%2,%3}, [%4];"
                     : "=r"(a1[0]), "=r"(a1[1]), "=r"(a1[2]), "=r"(a1[3]) : "r"(base + 32));
    }

    const int r0 = lane >> 2;
    const int j  = lane & 3;
    const size_t nlo = (size_t)bid * 128 + warp * 16 + r0;
    __half* plo = g_contrib16 + nlo * NCOL + j * 8;
    __half* phi = plo + (size_t)8 * NCOL;
    const uint2* bf = reinterpret_cast<const uint2*>(g_bfrag) + lane;

    for (int kb = 0; kb < 27; ++kb) {
        uint2 b[8];
#pragma unroll
        for (int q = 0; q < 8; ++q) b[q] = bf[(kb * 8 + q) * 32];

        unsigned hlo[4], hhi[4];
#pragma unroll
        for (int t = 0; t < 4; ++t) {
            float d0 = 0.f, d1 = 0.f, d2 = 0.f, d3 = 0.f;
            asm volatile(
                "mma.sync.aligned.m16n8k16.row.col.f32.f16.f16.f32 "
                "{%0,%1,%2,%3}, {%4,%5,%6,%7}, {%8,%9}, {%0,%1,%2,%3};"
                : "+f"(d0), "+f"(d1), "+f"(d2), "+f"(d3)
                : "r"(a0[0]), "r"(a0[1]), "r"(a0[2]), "r"(a0[3]),
                  "r"(b[t * 2].x), "r"(b[t * 2].y));
            asm volatile(
                "mma.sync.aligned.m16n8k16.row.col.f32.f16.f16.f32 "
                "{%0,%1,%2,%3}, {%4,%5,%6,%7}, {%8,%9}, {%0,%1,%2,%3};"
                : "+f"(d0), "+f"(d1), "+f"(d2), "+f"(d3)
                : "r"(a1[0]), "r"(a1[1]), "r"(a1[2]), "r"(a1[3]),
                  "r"(b[t * 2 + 1].x), "r"(b[t * 2 + 1].y));
            __half2 l2 = __floats2half2_rn(d0, d1);
            __half2 h2 = __floats2half2_rn(d2, d3);
            hlo[t] = *reinterpret_cast<unsigned*>(&l2);
            hhi[t] = *reinterpret_cast<unsigned*>(&h2);
        }
        uint4 vlo = make_uint4(hlo[0], hlo[1], hlo[2], hlo[3]);
        uint4 vhi = make_uint4(hhi[0], hhi[1], hhi[2], hhi[3]);
        __stcs(reinterpret_cast<uint4*>(plo + kb * 32), vlo);
        __stcs(reinterpret_cast<uint4*>(phi + kb * 32), vhi);
    }
}

// -------- 3. gather: out[m][perm] = sum over bucket of contrib16[e][:] ------
// Verbatim from the 182.7us R4 kernel: warp = node; lanes 0-15 entry A /
// 16-31 entry B per pair; 16-entry MLP unroll; evict-first loads.
__global__ __launch_bounds__(256) void k_gather(float* __restrict__ out) {
    int m = (blockIdx.x * blockDim.x + threadIdx.x) >> 5;
    if (m >= NN) return;
    const int lane = threadIdx.x & 31;
    const int hsel = lane >> 4;
    const int ch2  = lane & 15;
    int cnt = g_fill[m];
    if (cnt > CAP) cnt = CAP;
    const int* lst = g_list + (size_t)m * CAP;

    float2 acc = make_float2(0.f, 0.f);
    int j = 0;
    for (; j + 16 <= cnt; j += 16) {
        __half2 v[8];
#pragma unroll
        for (int t = 0; t < 8; ++t) {
            int e = lst[j + 2 * t + hsel];
            v[t]  = __ldcs(reinterpret_cast<const __half2*>(
                        g_contrib16 + (size_t)e * C + ch2 * 2));
        }
#pragma unroll
        for (int t = 0; t < 8; ++t) {
            float2 f = __half22float2(v[t]);
            acc.x += f.x; acc.y += f.y;
        }
    }
    for (; j + 2 <= cnt; j += 2) {
        int     e = lst[j + hsel];
        __half2 v = __ldcs(reinterpret_cast<const __half2*>(
                        g_contrib16 + (size_t)e * C + ch2 * 2));
        float2  f = __half22float2(v);
        acc.x += f.x; acc.y += f.y;
    }
    if (j < cnt && hsel == 0) {
        int     e = lst[j];
        __half2 v = __ldcs(reinterpret_cast<const __half2*>(
                        g_contrib16 + (size_t)e * C + ch2 * 2));
        float2  f = __half22float2(v);
        acc.x += f.x; acc.y += f.y;
    }
    acc.x += __shfl_down_sync(0xffffffffu, acc.x, 16);
    acc.y += __shfl_down_sync(0xffffffffu, acc.y, 16);
    if (hsel == 0) {
        int co = (ch2 & 3) * 8 + (ch2 >> 2) * 2;   // undo column permutation
        *reinterpret_cast<float2*>(out + (size_t)m * C + co) = acc;
    }
}

// -------- 4. BN stats, stage 1: float4-vectorized deterministic partials ----
// block = 128 rows; thread t reads float4 of channels g*4.. (g = t&7) at row
// (t>>3) + 32*iter; 4 iters. Deterministic cross-thread reduction via smem.
__global__ __launch_bounds__(256) void k_bnpart(const float* __restrict__ out) {
    __shared__ float4 ss4[256], sq4[256];
    const int tid = threadIdx.x;
    const float4* src = reinterpret_cast<const float4*>(out) +
                        (size_t)blockIdx.x * 1024 + tid;
    float4 s = make_float4(0.f, 0.f, 0.f, 0.f);
    float4 q = make_float4(0.f, 0.f, 0.f, 0.f);
#pragma unroll
    for (int it = 0; it < 4; ++it) {
        float4 v = src[it * 256];
        s.x += v.x; s.y += v.y; s.z += v.z; s.w += v.w;
        q.x += v.x * v.x; q.y += v.y * v.y; q.z += v.z * v.z; q.w += v.w * v.w;
    }
    ss4[tid] = s; sq4[tid] = q;
    __syncthreads();
    if (tid < 32) {                      // tid = channel; g = tid>>2, comp = tid&3
        int g = tid >> 2, comp = tid & 3;
        float S = 0.f, Q = 0.f;
#pragma unroll
        for (int r = 0; r < 32; ++r) {
            const float* sp = reinterpret_cast<const float*>(&ss4[r * 8 + g]);
            const float* qp = reinterpret_cast<const float*>(&sq4[r * 8 + g]);
            S += sp[comp];
            Q += qp[comp];
        }
        g_part[blockIdx.x * 64 + tid]      = S;
        g_part[blockIdx.x * 64 + 32 + tid] = Q;
    }
}

// -------- 5. BN stats, stage 2: final mean/var -> fused scale/shift ---------
__global__ __launch_bounds__(256) void k_bnfinal(const float* __restrict__ gamma,
                                                 const float* __restrict__ beta) {
    __shared__ float ss[8][32], sq[8][32];
    int ch = threadIdx.x & 31, w = threadIdx.x >> 5;
    float S = 0.f, Q = 0.f;
    for (int b = w; b < BN_BLKS; b += 8) {
        S += g_part[b * 64 + ch];
        Q += g_part[b * 64 + 32 + ch];
    }
    ss[w][ch] = S;
    sq[w][ch] = Q;
    __syncthreads();
    if (w == 0) {
        float St = 0.f, Qt = 0.f;
#pragma unroll
        for (int t = 0; t < 8; ++t) { St += ss[t][ch]; Qt += sq[t][ch]; }
        float mean  = St * (1.0f / NN);
        float var   = Qt * (1.0f / NN) - mean * mean;
        float rstd  = rsqrtf(var + EPS_F);
        float scale = gamma[ch] * rstd;
        g_stats[ch]      = scale;
        g_stats[32 + ch] = beta[ch] - mean * scale;
    }
}

// -------- 6. apply BN + ReLU: float4-vectorized --------
__global__ __launch_bounds__(256) void k_apply(float* __restrict__ out) {
    int i4 = blockIdx.x * blockDim.x + threadIdx.x;
    if (i4 >= NN * C / 4) return;
    int cb = (i4 & 7) * 4;               // channel base of this float4
    float4 v = reinterpret_cast<float4*>(out)[i4];
    v.x = fmaxf(fmaf(v.x, g_stats[cb + 0], g_stats[32 + cb + 0]), 0.f);
    v.y = fmaxf(fmaf(v.y, g_stats[cb + 1], g_stats[32 + cb + 1]), 0.f);
    v.z = fmaxf(fmaf(v.z, g_stats[cb + 2], g_stats[32 + cb + 2]), 0.f);
    v.w = fmaxf(fmaf(v.w, g_stats[cb + 3], g_stats[32 + cb + 3]), 0.f);
    reinterpret_cast<float4*>(out)[i4] = v;
}

extern "C" void kernel_launch(void* const* d_in, const int* in_sizes, int n_in,
                              void* d_out, int out_size) {
    const float* data   = (const float*)d_in[0];
    const float* weight = (const float*)d_in[1];
    const float* gamma  = (const float*)d_in[2];
    const float* beta   = (const float*)d_in[3];
    const int*   neigh  = (const int*)d_in[4];
    float*       out    = (float*)d_out;

    k_init<<<NN / 256, 256>>>(weight);
    k_work<<<GEMM_BLKS + FILL_BLKS, 256>>>(data, neigh);
    k_gather<<<(NN * 32 + 255) / 256, 256>>>(out);
    k_bnpart<<<BN_BLKS, 256>>>(out);
    k_bnfinal<<<1, 256>>>(gamma, beta);
    k_apply<<<(NN * C / 4 + 255) / 256, 256>>>(out);
}